// round 1
// baseline (speedup 1.0000x reference)
#include <cuda_runtime.h>

#define NB   1024
#define NS1  25
#define NS2  10
#define DF   128
#define ROWS1 (NB * NS1)   // 25600

// ---------------- scratch (no allocations allowed) ----------------
__device__ float g_X1[(size_t)ROWS1 * 256];  // [25600][self(128) | meanS2(128)]
__device__ float g_Y1[(size_t)ROWS1 * 256];  // relu(concat) per (b,s1)
__device__ float g_X0[(size_t)NB * 256];     // [1024][self | meanS1(h1)]
__device__ float g_Y0[(size_t)NB * 256];     // n0
__device__ float g_M1[(size_t)NB * 256];     // mean over s1 of Y1

// ---------------- kernel 1: gather h1 self + mean over S2 of h2 ----------------
// one warp per (b,s1) row; lane covers 4 floats (float4) of the 128-wide feature row
__global__ void gather1_kernel(const float* __restrict__ feat,
                               const int* __restrict__ s1,
                               const int* __restrict__ s2) {
    int warp = (blockIdx.x * blockDim.x + threadIdx.x) >> 5;
    int lane = threadIdx.x & 31;
    if (warp >= ROWS1) return;
    int c = lane * 4;

    long iself = s1[warp];
    float4 sv = *(const float4*)(feat + iself * DF + c);
    *(float4*)(g_X1 + (size_t)warp * 256 + c) = sv;

    const int* p = s2 + (size_t)warp * NS2;
    int idx[NS2];
#pragma unroll
    for (int j = 0; j < NS2; j++) idx[j] = p[j];

    float4 acc = make_float4(0.f, 0.f, 0.f, 0.f);
#pragma unroll
    for (int j = 0; j < NS2; j++) {
        float4 v = *(const float4*)(feat + (long)idx[j] * DF + c);
        acc.x += v.x; acc.y += v.y; acc.z += v.z; acc.w += v.w;
    }
    const float s = 1.0f / NS2;
    acc.x *= s; acc.y *= s; acc.z *= s; acc.w *= s;
    *(float4*)(g_X1 + (size_t)warp * 256 + 128 + c) = acc;
}

// ---------------- kernel 2: gather h0 self + mean over S1 of h1 ----------------
// mean over s1 of h1 == mean of the self-halves already staged in g_X1 (sequential reads)
__global__ void gather0_kernel(const float* __restrict__ feat,
                               const int* __restrict__ s0) {
    int warp = (blockIdx.x * blockDim.x + threadIdx.x) >> 5;
    int lane = threadIdx.x & 31;
    if (warp >= NB) return;
    int c = lane * 4;

    long iself = s0[warp];
    *(float4*)(g_X0 + (size_t)warp * 256 + c) =
        *(const float4*)(feat + iself * DF + c);

    float4 acc = make_float4(0.f, 0.f, 0.f, 0.f);
#pragma unroll
    for (int j = 0; j < NS1; j++) {
        float4 v = *(const float4*)(g_X1 + ((size_t)warp * NS1 + j) * 256 + c);
        acc.x += v.x; acc.y += v.y; acc.z += v.z; acc.w += v.w;
    }
    const float s = 1.0f / NS1;
    acc.x *= s; acc.y *= s; acc.z *= s; acc.w *= s;
    *(float4*)(g_X0 + (size_t)warp * 256 + 128 + c) = acc;
}

// ---------------- GEMM + ReLU ----------------
// out[row][half*128 + n] = relu( A_half[row][0:K] @ W_half[K][128] )
// BM=64 rows/block, BN=128 (full), full-K smem residency (K=128 or 256).
// 256 threads, each computes a 4x8 micro-tile (32 accs). A staged transposed
// in smem so the 4-row read is one LDS.128. All row strides are 256.
template <int K>
__global__ __launch_bounds__(256)
void gemm_relu_kernel(const float* __restrict__ A0, const float* __restrict__ W0,
                      const float* __restrict__ A1, const float* __restrict__ W1,
                      float* __restrict__ out) {
    extern __shared__ float sm[];
    float* As = sm;             // [K][64]
    float* Bs = sm + K * 64;    // [K][128]

    const float* A = blockIdx.y ? A1 : A0;
    const float* W = blockIdx.y ? W1 : W0;
    const int row0 = blockIdx.x * 64;
    const int tid = threadIdx.x;

    // stage A tile transposed: As[k][r]
    for (int idx = tid; idx < 64 * (K / 4); idx += 256) {
        int r  = idx / (K / 4);
        int k4 = (idx % (K / 4)) * 4;
        float4 v = *(const float4*)(A + (size_t)(row0 + r) * 256 + k4);
        As[(k4 + 0) * 64 + r] = v.x;
        As[(k4 + 1) * 64 + r] = v.y;
        As[(k4 + 2) * 64 + r] = v.z;
        As[(k4 + 3) * 64 + r] = v.w;
    }
    // stage W straight: Bs[k][n]
    for (int idx = tid; idx < K * 32; idx += 256) {
        ((float4*)Bs)[idx] = ((const float4*)W)[idx];
    }
    __syncthreads();

    const int r0 = (tid % 16) * 4;
    const int c0 = (tid / 16) * 8;

    float acc[4][8];
#pragma unroll
    for (int i = 0; i < 4; i++)
#pragma unroll
        for (int j = 0; j < 8; j++) acc[i][j] = 0.f;

#pragma unroll 8
    for (int k = 0; k < K; k++) {
        float4 a  = *(const float4*)(As + k * 64 + r0);
        float4 b0 = *(const float4*)(Bs + k * 128 + c0);
        float4 b1 = *(const float4*)(Bs + k * 128 + c0 + 4);
        float av[4] = {a.x, a.y, a.z, a.w};
        float bv[8] = {b0.x, b0.y, b0.z, b0.w, b1.x, b1.y, b1.z, b1.w};
#pragma unroll
        for (int i = 0; i < 4; i++)
#pragma unroll
            for (int j = 0; j < 8; j++)
                acc[i][j] += av[i] * bv[j];
    }

    const int ncol = blockIdx.y * 128 + c0;
#pragma unroll
    for (int i = 0; i < 4; i++) {
        float4 o0, o1;
        o0.x = fmaxf(acc[i][0], 0.f); o0.y = fmaxf(acc[i][1], 0.f);
        o0.z = fmaxf(acc[i][2], 0.f); o0.w = fmaxf(acc[i][3], 0.f);
        o1.x = fmaxf(acc[i][4], 0.f); o1.y = fmaxf(acc[i][5], 0.f);
        o1.z = fmaxf(acc[i][6], 0.f); o1.w = fmaxf(acc[i][7], 0.f);
        float* orow = out + (size_t)(row0 + r0 + i) * 256 + ncol;
        *(float4*)(orow)     = o0;
        *(float4*)(orow + 4) = o1;
    }
}

// ---------------- kernel 5: mean over S1 of Y1 -> M1 ----------------
__global__ void mean25_kernel() {
    int t = blockIdx.x * blockDim.x + threadIdx.x;   // 65536 threads
    if (t >= NB * 64) return;
    int b = t >> 6;
    int q = t & 63;
    const float4* base = (const float4*)g_Y1 + (size_t)b * NS1 * 64 + q;
    float4 acc = make_float4(0.f, 0.f, 0.f, 0.f);
#pragma unroll
    for (int j = 0; j < NS1; j++) {
        float4 v = base[(size_t)j * 64];
        acc.x += v.x; acc.y += v.y; acc.z += v.z; acc.w += v.w;
    }
    const float s = 1.0f / NS1;
    acc.x *= s; acc.y *= s; acc.z *= s; acc.w *= s;
    ((float4*)g_M1)[(size_t)b * 64 + q] = acc;
}

// ---------------- launch ----------------
extern "C" void kernel_launch(void* const* d_in, const int* in_sizes, int n_in,
                              void* d_out, int out_size) {
    const float* feat = (const float*)d_in[0];
    const float* ws0  = (const float*)d_in[1];
    const float* wn0  = (const float*)d_in[2];
    const float* ws1  = (const float*)d_in[3];
    const float* wn1  = (const float*)d_in[4];
    const int*   s0   = (const int*)d_in[5];
    const int*   s1   = (const int*)d_in[6];
    const int*   s2   = (const int*)d_in[7];
    float* out = (float*)d_out;

    float *pX1, *pX0, *pY0, *pM1, *pY1;
    cudaGetSymbolAddress((void**)&pX1, g_X1);
    cudaGetSymbolAddress((void**)&pY1, g_Y1);
    cudaGetSymbolAddress((void**)&pX0, g_X0);
    cudaGetSymbolAddress((void**)&pY0, g_Y0);
    cudaGetSymbolAddress((void**)&pM1, g_M1);

    const size_t sm128 = (size_t)(128 * 64 + 128 * 128) * sizeof(float);  //  96 KB
    const size_t sm256 = (size_t)(256 * 64 + 256 * 128) * sizeof(float);  // 192 KB
    cudaFuncSetAttribute(gemm_relu_kernel<128>,
                         cudaFuncAttributeMaxDynamicSharedMemorySize, (int)sm128);
    cudaFuncSetAttribute(gemm_relu_kernel<256>,
                         cudaFuncAttributeMaxDynamicSharedMemorySize, (int)sm256);

    // 1) X1 = [h1_self | mean_S2(h2)]  (dominant gather)
    gather1_kernel<<<(ROWS1 * 32 + 255) / 256, 256>>>(feat, s1, s2);
    // 2) X0 = [h0 | mean_S1(h1)]  (reads X1 self halves sequentially)
    gather0_kernel<<<(NB * 32 + 255) / 256, 256>>>(feat, s0);
    // 3) Y1 = relu([X1s@Ws0 | X1n@Wn0])   (25600 rows)
    gemm_relu_kernel<128><<<dim3(ROWS1 / 64, 2), 256, sm128>>>(pX1, ws0, pX1 + 128, wn0, pY1);
    // 4) Y0 = relu([X0s@Ws0 | X0n@Wn0])   (1024 rows)
    gemm_relu_kernel<128><<<dim3(NB / 64, 2), 256, sm128>>>(pX0, ws0, pX0 + 128, wn0, pY0);
    // 5) M1 = mean_S1(Y1)
    mean25_kernel<<<(NB * 64 + 255) / 256, 256>>>();
    // 6) out = relu([Y0@Ws1 | M1@Wn1])
    gemm_relu_kernel<256><<<dim3(NB / 64, 2), 256, sm256>>>(pY0, ws1, pM1, wn1, out);
}

// round 2
// speedup vs baseline: 1.0790x; 1.0790x over previous
#include <cuda_runtime.h>

#define NB   1024
#define NS1  25
#define NS2  10
#define DF   128
#define ROWS1 (NB * NS1)   // 25600

// ---------------- scratch (no allocations allowed) ----------------
__device__ float g_X1[(size_t)ROWS1 * 256];  // [25600][self(128) | meanS2(128)]
__device__ float g_Y1[(size_t)ROWS1 * 256];  // relu(concat) per (b,s1)
__device__ float g_X0[(size_t)NB * 256];     // [1024][self | meanS1(h1)]
__device__ float g_Y0[(size_t)NB * 256];     // n0
__device__ float g_M1[(size_t)NB * 256];     // mean over s1 of Y1

// ---------------- f32x2 packed helpers ----------------
__device__ __forceinline__ unsigned long long splat2(float x) {
    unsigned long long r;
    asm("mov.b64 %0, {%1, %1};" : "=l"(r) : "r"(__float_as_uint(x)));
    return r;
}
__device__ __forceinline__ void ffma2(unsigned long long& acc,
                                      unsigned long long a,
                                      unsigned long long b) {
    asm("fma.rn.f32x2 %0, %1, %2, %0;" : "+l"(acc) : "l"(a), "l"(b));
}
__device__ __forceinline__ void unpack2(unsigned long long v, float& lo, float& hi) {
    unsigned int l, h;
    asm("mov.b64 {%0, %1}, %2;" : "=r"(l), "=r"(h) : "l"(v));
    lo = __uint_as_float(l);
    hi = __uint_as_float(h);
}

// ---------------- kernel 1: gather h1 self + mean over S2 of h2 ----------------
__global__ void gather1_kernel(const float* __restrict__ feat,
                               const int* __restrict__ s1,
                               const int* __restrict__ s2) {
    int warp = (blockIdx.x * blockDim.x + threadIdx.x) >> 5;
    int lane = threadIdx.x & 31;
    if (warp >= ROWS1) return;
    int c = lane * 4;

    long iself = s1[warp];
    float4 sv = *(const float4*)(feat + iself * DF + c);
    *(float4*)(g_X1 + (size_t)warp * 256 + c) = sv;

    const int* p = s2 + (size_t)warp * NS2;
    int idx[NS2];
#pragma unroll
    for (int j = 0; j < NS2; j++) idx[j] = p[j];

    float4 acc = make_float4(0.f, 0.f, 0.f, 0.f);
#pragma unroll
    for (int j = 0; j < NS2; j++) {
        float4 v = *(const float4*)(feat + (long)idx[j] * DF + c);
        acc.x += v.x; acc.y += v.y; acc.z += v.z; acc.w += v.w;
    }
    const float s = 1.0f / NS2;
    acc.x *= s; acc.y *= s; acc.z *= s; acc.w *= s;
    *(float4*)(g_X1 + (size_t)warp * 256 + 128 + c) = acc;
}

// ---------------- kernel 2: gather h0 self + mean over S1 of h1 ----------------
__global__ void gather0_kernel(const float* __restrict__ feat,
                               const int* __restrict__ s0) {
    int warp = (blockIdx.x * blockDim.x + threadIdx.x) >> 5;
    int lane = threadIdx.x & 31;
    if (warp >= NB) return;
    int c = lane * 4;

    long iself = s0[warp];
    *(float4*)(g_X0 + (size_t)warp * 256 + c) =
        *(const float4*)(feat + iself * DF + c);

    float4 acc = make_float4(0.f, 0.f, 0.f, 0.f);
#pragma unroll
    for (int j = 0; j < NS1; j++) {
        float4 v = *(const float4*)(g_X1 + ((size_t)warp * NS1 + j) * 256 + c);
        acc.x += v.x; acc.y += v.y; acc.z += v.z; acc.w += v.w;
    }
    const float s = 1.0f / NS1;
    acc.x *= s; acc.y *= s; acc.z *= s; acc.w *= s;
    *(float4*)(g_X0 + (size_t)warp * 256 + 128 + c) = acc;
}

// ---------------- big GEMM + ReLU (f32x2 packed FMA) ----------------
// out[row][half*128 + n] = relu( A_half[row][0:128] @ W_half[128][128] )
// BM=64, BN=128, full-K smem. 256 threads, 4x8 micro-tile as 4x4 f32x2 pairs.
__global__ __launch_bounds__(256)
void gemm_big_kernel(const float* __restrict__ A0, const float* __restrict__ W0,
                     const float* __restrict__ A1, const float* __restrict__ W1,
                     float* __restrict__ out) {
    const int K = 128;
    extern __shared__ float sm[];
    float* As = sm;             // [K][64] (transposed)
    float* Bs = sm + K * 64;    // [K][128]

    const float* A = blockIdx.y ? A1 : A0;
    const float* W = blockIdx.y ? W1 : W0;
    const int row0 = blockIdx.x * 64;
    const int tid = threadIdx.x;

    // stage A tile transposed: As[k][r]
    for (int idx = tid; idx < 64 * (K / 4); idx += 256) {
        int r  = idx / (K / 4);
        int k4 = (idx % (K / 4)) * 4;
        float4 v = *(const float4*)(A + (size_t)(row0 + r) * 256 + k4);
        As[(k4 + 0) * 64 + r] = v.x;
        As[(k4 + 1) * 64 + r] = v.y;
        As[(k4 + 2) * 64 + r] = v.z;
        As[(k4 + 3) * 64 + r] = v.w;
    }
    // stage W straight: Bs[k][n]
    for (int idx = tid; idx < K * 32; idx += 256) {
        ((float4*)Bs)[idx] = ((const float4*)W)[idx];
    }
    __syncthreads();

    const int r0 = (tid % 16) * 4;
    const int c0 = (tid / 16) * 8;

    unsigned long long acc2[4][4];
#pragma unroll
    for (int i = 0; i < 4; i++)
#pragma unroll
        for (int j = 0; j < 4; j++) acc2[i][j] = 0ULL;

#pragma unroll 8
    for (int k = 0; k < K; k++) {
        float4 a = *(const float4*)(As + k * 64 + r0);
        ulonglong2 b01 = *(const ulonglong2*)(Bs + k * 128 + c0);
        ulonglong2 b23 = *(const ulonglong2*)(Bs + k * 128 + c0 + 4);
        unsigned long long av2[4];
        av2[0] = splat2(a.x); av2[1] = splat2(a.y);
        av2[2] = splat2(a.z); av2[3] = splat2(a.w);
#pragma unroll
        for (int i = 0; i < 4; i++) {
            ffma2(acc2[i][0], av2[i], b01.x);
            ffma2(acc2[i][1], av2[i], b01.y);
            ffma2(acc2[i][2], av2[i], b23.x);
            ffma2(acc2[i][3], av2[i], b23.y);
        }
    }

    const int ncol = blockIdx.y * 128 + c0;
#pragma unroll
    for (int i = 0; i < 4; i++) {
        float v[8];
#pragma unroll
        for (int j = 0; j < 4; j++) unpack2(acc2[i][j], v[2 * j], v[2 * j + 1]);
        float4 o0, o1;
        o0.x = fmaxf(v[0], 0.f); o0.y = fmaxf(v[1], 0.f);
        o0.z = fmaxf(v[2], 0.f); o0.w = fmaxf(v[3], 0.f);
        o1.x = fmaxf(v[4], 0.f); o1.y = fmaxf(v[5], 0.f);
        o1.z = fmaxf(v[6], 0.f); o1.w = fmaxf(v[7], 0.f);
        float* orow = out + (size_t)(row0 + r0 + i) * 256 + ncol;
        *(float4*)(orow)     = o0;
        *(float4*)(orow + 4) = o1;
    }
}

// ---------------- small GEMM + ReLU (latency-optimal, many blocks) ----------------
// 1024 rows only. BM=8 rows/block, grid (128, 2). 256 threads = 8 warps;
// warp w owns row row0+w; lane computes 4 consecutive cols. W streamed from
// gmem (L1/L2-resident: 128 blocks reuse the same 128KB max of W).
template <int K>
__global__ __launch_bounds__(256)
void gemm_small_kernel(const float* __restrict__ A0, const float* __restrict__ W0,
                       const float* __restrict__ A1, const float* __restrict__ W1,
                       float* __restrict__ out) {
    __shared__ float As[8 * K];

    const float* A = blockIdx.y ? A1 : A0;
    const float* W = blockIdx.y ? W1 : W0;
    const int row0 = blockIdx.x * 8;
    const int tid = threadIdx.x;
    const int w = tid >> 5;          // row within tile
    const int lane = tid & 31;
    const int c0 = lane * 4;

    // stage 8 rows of A (row stride in gmem is 256)
    for (int idx = tid; idx < 8 * (K / 4); idx += 256) {
        int r  = idx / (K / 4);
        int k4 = (idx % (K / 4)) * 4;
        *(float4*)(As + r * K + k4) =
            *(const float4*)(A + (size_t)(row0 + r) * 256 + k4);
    }
    __syncthreads();

    float4 acc = make_float4(0.f, 0.f, 0.f, 0.f);
    const float* arow = As + w * K;
#pragma unroll 4
    for (int k = 0; k < K; k++) {
        float a = arow[k];
        float4 b = *(const float4*)(W + (size_t)k * 128 + c0);
        acc.x = fmaf(a, b.x, acc.x);
        acc.y = fmaf(a, b.y, acc.y);
        acc.z = fmaf(a, b.z, acc.z);
        acc.w = fmaf(a, b.w, acc.w);
    }

    acc.x = fmaxf(acc.x, 0.f); acc.y = fmaxf(acc.y, 0.f);
    acc.z = fmaxf(acc.z, 0.f); acc.w = fmaxf(acc.w, 0.f);
    *(float4*)(out + (size_t)(row0 + w) * 256 + blockIdx.y * 128 + c0) = acc;
}

// ---------------- kernel 5: mean over S1 of Y1 -> M1 ----------------
__global__ void mean25_kernel() {
    int t = blockIdx.x * blockDim.x + threadIdx.x;   // 65536 threads
    if (t >= NB * 64) return;
    int b = t >> 6;
    int q = t & 63;
    const float4* base = (const float4*)g_Y1 + (size_t)b * NS1 * 64 + q;
    float4 acc = make_float4(0.f, 0.f, 0.f, 0.f);
#pragma unroll
    for (int j = 0; j < NS1; j++) {
        float4 v = base[(size_t)j * 64];
        acc.x += v.x; acc.y += v.y; acc.z += v.z; acc.w += v.w;
    }
    const float s = 1.0f / NS1;
    acc.x *= s; acc.y *= s; acc.z *= s; acc.w *= s;
    ((float4*)g_M1)[(size_t)b * 64 + q] = acc;
}

// ---------------- launch ----------------
extern "C" void kernel_launch(void* const* d_in, const int* in_sizes, int n_in,
                              void* d_out, int out_size) {
    const float* feat = (const float*)d_in[0];
    const float* ws0  = (const float*)d_in[1];
    const float* wn0  = (const float*)d_in[2];
    const float* ws1  = (const float*)d_in[3];
    const float* wn1  = (const float*)d_in[4];
    const int*   s0   = (const int*)d_in[5];
    const int*   s1   = (const int*)d_in[6];
    const int*   s2   = (const int*)d_in[7];
    float* out = (float*)d_out;

    float *pX1, *pX0, *pY0, *pM1, *pY1;
    cudaGetSymbolAddress((void**)&pX1, g_X1);
    cudaGetSymbolAddress((void**)&pY1, g_Y1);
    cudaGetSymbolAddress((void**)&pX0, g_X0);
    cudaGetSymbolAddress((void**)&pY0, g_Y0);
    cudaGetSymbolAddress((void**)&pM1, g_M1);

    const size_t smBig = (size_t)(128 * 64 + 128 * 128) * sizeof(float);  // 96 KB
    cudaFuncSetAttribute(gemm_big_kernel,
                         cudaFuncAttributeMaxDynamicSharedMemorySize, (int)smBig);

    // 1) X1 = [h1_self | mean_S2(h2)]  (dominant gather)
    gather1_kernel<<<(ROWS1 * 32 + 255) / 256, 256>>>(feat, s1, s2);
    // 2) X0 = [h0 | mean_S1(h1)]
    gather0_kernel<<<(NB * 32 + 255) / 256, 256>>>(feat, s0);
    // 3) Y1 = relu([X1s@Ws0 | X1n@Wn0])   (25600 rows, f32x2)
    gemm_big_kernel<<<dim3(ROWS1 / 64, 2), 256, smBig>>>(pX1, ws0, pX1 + 128, wn0, pY1);
    // 4) Y0 = relu([X0s@Ws0 | X0n@Wn0])   (1024 rows, many-block)
    gemm_small_kernel<128><<<dim3(NB / 8, 2), 256>>>(pX0, ws0, pX0 + 128, wn0, pY0);
    // 5) M1 = mean_S1(Y1)
    mean25_kernel<<<(NB * 64 + 255) / 256, 256>>>();
    // 6) out = relu([Y0@Ws1 | M1@Wn1])
    gemm_small_kernel<256><<<dim3(NB / 8, 2), 256>>>(pY0, ws1, pM1, wn1, out);
}

// round 3
// speedup vs baseline: 1.2097x; 1.1211x over previous
#include <cuda_runtime.h>

#define NB   1024
#define NS1  25
#define NS2  10
#define DF   128
#define ROWS1 (NB * NS1)   // 25600

// ---------------- scratch (no allocations allowed) ----------------
__device__ float g_X1[(size_t)ROWS1 * 256];  // [25600][self(128) | meanS2(128)]
__device__ float g_Y1[(size_t)ROWS1 * 256];  // relu(concat) per (b,s1)
__device__ float g_X0[(size_t)NB * 256];     // [1024][self | meanS1(h1)]
__device__ float g_Y0[(size_t)NB * 256];     // n0
__device__ float g_M1[(size_t)NB * 256];     // mean over s1 of Y1

// ---------------- f32x2 packed helpers ----------------
__device__ __forceinline__ unsigned long long splat2(float x) {
    unsigned long long r;
    asm("mov.b64 %0, {%1, %1};" : "=l"(r) : "r"(__float_as_uint(x)));
    return r;
}
__device__ __forceinline__ void ffma2(unsigned long long& acc,
                                      unsigned long long a,
                                      unsigned long long b) {
    asm("fma.rn.f32x2 %0, %1, %2, %0;" : "+l"(acc) : "l"(a), "l"(b));
}
__device__ __forceinline__ void unpack2(unsigned long long v, float& lo, float& hi) {
    unsigned int l, h;
    asm("mov.b64 {%0, %1}, %2;" : "=r"(l), "=r"(h) : "l"(v));
    lo = __uint_as_float(l);
    hi = __uint_as_float(h);
}

// ---------------- kernel 1: gather h1 self + mean over S2 of h2 ----------------
__global__ void gather1_kernel(const float* __restrict__ feat,
                               const int* __restrict__ s1,
                               const int* __restrict__ s2) {
    int warp = (blockIdx.x * blockDim.x + threadIdx.x) >> 5;
    int lane = threadIdx.x & 31;
    if (warp >= ROWS1) return;
    int c = lane * 4;

    long iself = s1[warp];
    float4 sv = *(const float4*)(feat + iself * DF + c);
    *(float4*)(g_X1 + (size_t)warp * 256 + c) = sv;

    const int* p = s2 + (size_t)warp * NS2;
    int idx[NS2];
#pragma unroll
    for (int j = 0; j < NS2; j++) idx[j] = p[j];

    float4 acc = make_float4(0.f, 0.f, 0.f, 0.f);
#pragma unroll
    for (int j = 0; j < NS2; j++) {
        float4 v = *(const float4*)(feat + (long)idx[j] * DF + c);
        acc.x += v.x; acc.y += v.y; acc.z += v.z; acc.w += v.w;
    }
    const float s = 1.0f / NS2;
    acc.x *= s; acc.y *= s; acc.z *= s; acc.w *= s;
    *(float4*)(g_X1 + (size_t)warp * 256 + 128 + c) = acc;
}

// ---------------- kernel 2: gather h0 self + mean over S1 of h1 ----------------
__global__ void gather0_kernel(const float* __restrict__ feat,
                               const int* __restrict__ s0) {
    int warp = (blockIdx.x * blockDim.x + threadIdx.x) >> 5;
    int lane = threadIdx.x & 31;
    if (warp >= NB) return;
    int c = lane * 4;

    long iself = s0[warp];
    *(float4*)(g_X0 + (size_t)warp * 256 + c) =
        *(const float4*)(feat + iself * DF + c);

    float4 acc = make_float4(0.f, 0.f, 0.f, 0.f);
#pragma unroll
    for (int j = 0; j < NS1; j++) {
        float4 v = *(const float4*)(g_X1 + ((size_t)warp * NS1 + j) * 256 + c);
        acc.x += v.x; acc.y += v.y; acc.z += v.z; acc.w += v.w;
    }
    const float s = 1.0f / NS1;
    acc.x *= s; acc.y *= s; acc.z *= s; acc.w *= s;
    *(float4*)(g_X0 + (size_t)warp * 256 + 128 + c) = acc;
}

// ---------------- big GEMM + ReLU (f32x2 packed FMA) ----------------
__global__ __launch_bounds__(256)
void gemm_big_kernel(const float* __restrict__ A0, const float* __restrict__ W0,
                     const float* __restrict__ A1, const float* __restrict__ W1,
                     float* __restrict__ out) {
    const int K = 128;
    extern __shared__ float sm[];
    float* As = sm;             // [K][64] (transposed)
    float* Bs = sm + K * 64;    // [K][128]

    const float* A = blockIdx.y ? A1 : A0;
    const float* W = blockIdx.y ? W1 : W0;
    const int row0 = blockIdx.x * 64;
    const int tid = threadIdx.x;

    for (int idx = tid; idx < 64 * (K / 4); idx += 256) {
        int r  = idx / (K / 4);
        int k4 = (idx % (K / 4)) * 4;
        float4 v = *(const float4*)(A + (size_t)(row0 + r) * 256 + k4);
        As[(k4 + 0) * 64 + r] = v.x;
        As[(k4 + 1) * 64 + r] = v.y;
        As[(k4 + 2) * 64 + r] = v.z;
        As[(k4 + 3) * 64 + r] = v.w;
    }
    for (int idx = tid; idx < K * 32; idx += 256) {
        ((float4*)Bs)[idx] = ((const float4*)W)[idx];
    }
    __syncthreads();

    const int r0 = (tid % 16) * 4;
    const int c0 = (tid / 16) * 8;

    unsigned long long acc2[4][4];
#pragma unroll
    for (int i = 0; i < 4; i++)
#pragma unroll
        for (int j = 0; j < 4; j++) acc2[i][j] = 0ULL;

#pragma unroll 8
    for (int k = 0; k < K; k++) {
        float4 a = *(const float4*)(As + k * 64 + r0);
        ulonglong2 b01 = *(const ulonglong2*)(Bs + k * 128 + c0);
        ulonglong2 b23 = *(const ulonglong2*)(Bs + k * 128 + c0 + 4);
        unsigned long long av2[4];
        av2[0] = splat2(a.x); av2[1] = splat2(a.y);
        av2[2] = splat2(a.z); av2[3] = splat2(a.w);
#pragma unroll
        for (int i = 0; i < 4; i++) {
            ffma2(acc2[i][0], av2[i], b01.x);
            ffma2(acc2[i][1], av2[i], b01.y);
            ffma2(acc2[i][2], av2[i], b23.x);
            ffma2(acc2[i][3], av2[i], b23.y);
        }
    }

    const int ncol = blockIdx.y * 128 + c0;
#pragma unroll
    for (int i = 0; i < 4; i++) {
        float v[8];
#pragma unroll
        for (int j = 0; j < 4; j++) unpack2(acc2[i][j], v[2 * j], v[2 * j + 1]);
        float4 o0, o1;
        o0.x = fmaxf(v[0], 0.f); o0.y = fmaxf(v[1], 0.f);
        o0.z = fmaxf(v[2], 0.f); o0.w = fmaxf(v[3], 0.f);
        o1.x = fmaxf(v[4], 0.f); o1.y = fmaxf(v[5], 0.f);
        o1.z = fmaxf(v[6], 0.f); o1.w = fmaxf(v[7], 0.f);
        float* orow = out + (size_t)(row0 + r0 + i) * 256 + ncol;
        *(float4*)(orow)     = o0;
        *(float4*)(orow + 4) = o1;
    }
}

// ---------------- small GEMM + ReLU (tiled, W in smem) ----------------
// 1024 rows. Block computes 32 rows x 64 cols. grid (32, 4):
// blockIdx.y = output col-chunk (64 wide); half = y>>1 picks (A,W) pair,
// (y&1)*64 picks the W column offset. A staged transposed As_t[k][32],
// W tile Bs[k][64]. 256 threads, 2x4 micro-tile.
template <int K>
__global__ __launch_bounds__(256)
void gemm_small_kernel(const float* __restrict__ A0, const float* __restrict__ W0,
                       const float* __restrict__ A1, const float* __restrict__ W1,
                       float* __restrict__ out) {
    extern __shared__ float sm[];
    float* As = sm;             // [K][32] transposed
    float* Bs = sm + K * 32;    // [K][64]

    const int half = blockIdx.y >> 1;
    const float* A = half ? A1 : A0;
    const float* W = half ? W1 : W0;
    const int wcol0 = (blockIdx.y & 1) * 64;
    const int row0 = blockIdx.x * 32;
    const int tid = threadIdx.x;

    // stage A transposed: r inner so STS is conflict-free
    for (int idx = tid; idx < 32 * (K / 4); idx += 256) {
        int r  = idx & 31;
        int k4 = (idx >> 5) * 4;
        float4 v = *(const float4*)(A + (size_t)(row0 + r) * 256 + k4);
        As[(k4 + 0) * 32 + r] = v.x;
        As[(k4 + 1) * 32 + r] = v.y;
        As[(k4 + 2) * 32 + r] = v.z;
        As[(k4 + 3) * 32 + r] = v.w;
    }
    // stage W tile: Bs[k][0:64] = W[k][wcol0:wcol0+64]
    for (int idx = tid; idx < K * 16; idx += 256) {
        int k = idx >> 4;
        int j4 = (idx & 15) * 4;
        *(float4*)(Bs + k * 64 + j4) =
            *(const float4*)(W + (size_t)k * 128 + wcol0 + j4);
    }
    __syncthreads();

    const int rr = (tid & 15) * 2;
    const int cc = (tid >> 4) * 4;

    float acc[2][4];
#pragma unroll
    for (int i = 0; i < 2; i++)
#pragma unroll
        for (int j = 0; j < 4; j++) acc[i][j] = 0.f;

#pragma unroll 8
    for (int k = 0; k < K; k++) {
        float2 a = *(const float2*)(As + k * 32 + rr);
        float4 b = *(const float4*)(Bs + k * 64 + cc);
        acc[0][0] = fmaf(a.x, b.x, acc[0][0]);
        acc[0][1] = fmaf(a.x, b.y, acc[0][1]);
        acc[0][2] = fmaf(a.x, b.z, acc[0][2]);
        acc[0][3] = fmaf(a.x, b.w, acc[0][3]);
        acc[1][0] = fmaf(a.y, b.x, acc[1][0]);
        acc[1][1] = fmaf(a.y, b.y, acc[1][1]);
        acc[1][2] = fmaf(a.y, b.z, acc[1][2]);
        acc[1][3] = fmaf(a.y, b.w, acc[1][3]);
    }

    const int ncol = blockIdx.y * 64 + cc;
#pragma unroll
    for (int i = 0; i < 2; i++) {
        float4 o;
        o.x = fmaxf(acc[i][0], 0.f); o.y = fmaxf(acc[i][1], 0.f);
        o.z = fmaxf(acc[i][2], 0.f); o.w = fmaxf(acc[i][3], 0.f);
        *(float4*)(out + (size_t)(row0 + rr + i) * 256 + ncol) = o;
    }
}

// ---------------- mean over S1 of Y1 -> M1 ----------------
__global__ void mean25_kernel() {
    int t = blockIdx.x * blockDim.x + threadIdx.x;
    if (t >= NB * 64) return;
    int b = t >> 6;
    int q = t & 63;
    const float4* base = (const float4*)g_Y1 + (size_t)b * NS1 * 64 + q;
    float4 acc = make_float4(0.f, 0.f, 0.f, 0.f);
#pragma unroll
    for (int j = 0; j < NS1; j++) {
        float4 v = base[(size_t)j * 64];
        acc.x += v.x; acc.y += v.y; acc.z += v.z; acc.w += v.w;
    }
    const float s = 1.0f / NS1;
    acc.x *= s; acc.y *= s; acc.z *= s; acc.w *= s;
    ((float4*)g_M1)[(size_t)b * 64 + q] = acc;
}

// ---------------- launch ----------------
extern "C" void kernel_launch(void* const* d_in, const int* in_sizes, int n_in,
                              void* d_out, int out_size) {
    const float* feat = (const float*)d_in[0];
    const float* ws0  = (const float*)d_in[1];
    const float* wn0  = (const float*)d_in[2];
    const float* ws1  = (const float*)d_in[3];
    const float* wn1  = (const float*)d_in[4];
    const int*   s0   = (const int*)d_in[5];
    const int*   s1   = (const int*)d_in[6];
    const int*   s2   = (const int*)d_in[7];
    float* out = (float*)d_out;

    float *pX1, *pX0, *pY0, *pM1, *pY1;
    cudaGetSymbolAddress((void**)&pX1, g_X1);
    cudaGetSymbolAddress((void**)&pY1, g_Y1);
    cudaGetSymbolAddress((void**)&pX0, g_X0);
    cudaGetSymbolAddress((void**)&pY0, g_Y0);
    cudaGetSymbolAddress((void**)&pM1, g_M1);

    const size_t smBig = (size_t)(128 * 64 + 128 * 128) * sizeof(float);   // 96 KB
    const size_t smS128 = (size_t)(128 * 32 + 128 * 64) * sizeof(float);   // 48 KB
    const size_t smS256 = (size_t)(256 * 32 + 256 * 64) * sizeof(float);   // 96 KB
    cudaFuncSetAttribute(gemm_big_kernel,
                         cudaFuncAttributeMaxDynamicSharedMemorySize, (int)smBig);
    cudaFuncSetAttribute(gemm_small_kernel<128>,
                         cudaFuncAttributeMaxDynamicSharedMemorySize, (int)smS128);
    cudaFuncSetAttribute(gemm_small_kernel<256>,
                         cudaFuncAttributeMaxDynamicSharedMemorySize, (int)smS256);

    // 1) X1 = [h1_self | mean_S2(h2)]
    gather1_kernel<<<(ROWS1 * 32 + 255) / 256, 256>>>(feat, s1, s2);
    // 2) X0 = [h0 | mean_S1(h1)]
    gather0_kernel<<<(NB * 32 + 255) / 256, 256>>>(feat, s0);
    // 3) Y0 = relu([X0s@Ws0 | X0n@Wn0])   (moved earlier; only needs X0)
    gemm_small_kernel<128><<<dim3(NB / 32, 4), 256, smS128>>>(pX0, ws0, pX0 + 128, wn0, pY0);
    // 4) Y1 = relu([X1s@Ws0 | X1n@Wn0])   <-- position 4: gets profiled
    gemm_big_kernel<<<dim3(ROWS1 / 64, 2), 256, smBig>>>(pX1, ws0, pX1 + 128, wn0, pY1);
    // 5) M1 = mean_S1(Y1)
    mean25_kernel<<<(NB * 64 + 255) / 256, 256>>>();
    // 6) out = relu([Y0@Ws1 | M1@Wn1])
    gemm_small_kernel<256><<<dim3(NB / 32, 4), 256, smS256>>>(pY0, ws1, pM1, wn1, out);
}

// round 5
// speedup vs baseline: 1.4296x; 1.1818x over previous
#include <cuda_runtime.h>
#include <cuda_bf16.h>
#include <cstdint>

#define NB   1024
#define NS1  25
#define NS2  10
#define DF   128
#define ROWS1 (NB * NS1)   // 25600

// ---------------- scratch (no allocations allowed) ----------------
__device__ float g_X1[(size_t)ROWS1 * 256];  // [25600][self(128) | meanS2(128)]
__device__ float g_Y1[(size_t)ROWS1 * 256];  // relu(concat) per (b,s1)
__device__ float g_X0[(size_t)NB * 256];     // [1024][self | meanS1(h1)]
__device__ float g_Y0[(size_t)NB * 256];     // n0
__device__ float g_M1[(size_t)NB * 256];     // mean over s1 of Y1
__device__ __align__(16) __nv_bfloat16 g_WtH[2 * 128 * 128];  // W^T hi, [half][n][k]
__device__ __align__(16) __nv_bfloat16 g_WtL[2 * 128 * 128];  // W^T lo

// ---------------- prep: transpose + bf16-split the layer-0 weights ----------------
__global__ void prep_w_kernel(const float* __restrict__ w0,
                              const float* __restrict__ w1) {
    __shared__ float t[32][33];
    int b = blockIdx.x;
    int half = b >> 4;
    int tile = b & 15;
    int tr = (tile >> 2) * 32;   // k base
    int tc = (tile & 3) * 32;    // n base
    const float* W = half ? w1 : w0;
    int tx = threadIdx.x & 31, ty = threadIdx.x >> 5;   // 32x8
#pragma unroll
    for (int p = 0; p < 32; p += 8)
        t[ty + p][tx] = W[(size_t)(tr + ty + p) * 128 + tc + tx];
    __syncthreads();
#pragma unroll
    for (int p = 0; p < 32; p += 8) {
        int n = tc + ty + p, k = tr + tx;
        float v = t[tx][ty + p];
        __nv_bfloat16 h = __float2bfloat16(v);
        __nv_bfloat16 l = __float2bfloat16(v - __bfloat162float(h));
        size_t o = ((size_t)half * 128 + n) * 128 + k;
        g_WtH[o] = h;
        g_WtL[o] = l;
    }
}

// ---------------- gather kernels ----------------
__global__ void gather1_kernel(const float* __restrict__ feat,
                               const int* __restrict__ s1,
                               const int* __restrict__ s2) {
    int warp = (blockIdx.x * blockDim.x + threadIdx.x) >> 5;
    int lane = threadIdx.x & 31;
    if (warp >= ROWS1) return;
    int c = lane * 4;

    long iself = s1[warp];
    float4 sv = *(const float4*)(feat + iself * DF + c);
    *(float4*)(g_X1 + (size_t)warp * 256 + c) = sv;

    const int* p = s2 + (size_t)warp * NS2;
    int idx[NS2];
#pragma unroll
    for (int j = 0; j < NS2; j++) idx[j] = p[j];

    float4 acc = make_float4(0.f, 0.f, 0.f, 0.f);
#pragma unroll
    for (int j = 0; j < NS2; j++) {
        float4 v = *(const float4*)(feat + (long)idx[j] * DF + c);
        acc.x += v.x; acc.y += v.y; acc.z += v.z; acc.w += v.w;
    }
    const float s = 1.0f / NS2;
    acc.x *= s; acc.y *= s; acc.z *= s; acc.w *= s;
    *(float4*)(g_X1 + (size_t)warp * 256 + 128 + c) = acc;
}

__global__ void gather0_kernel(const float* __restrict__ feat,
                               const int* __restrict__ s0) {
    int warp = (blockIdx.x * blockDim.x + threadIdx.x) >> 5;
    int lane = threadIdx.x & 31;
    if (warp >= NB) return;
    int c = lane * 4;

    long iself = s0[warp];
    *(float4*)(g_X0 + (size_t)warp * 256 + c) =
        *(const float4*)(feat + iself * DF + c);

    float4 acc = make_float4(0.f, 0.f, 0.f, 0.f);
#pragma unroll
    for (int j = 0; j < NS1; j++) {
        float4 v = *(const float4*)(g_X1 + ((size_t)warp * NS1 + j) * 256 + c);
        acc.x += v.x; acc.y += v.y; acc.z += v.z; acc.w += v.w;
    }
    const float s = 1.0f / NS1;
    acc.x *= s; acc.y *= s; acc.z *= s; acc.w *= s;
    *(float4*)(g_X0 + (size_t)warp * 256 + 128 + c) = acc;
}

// ---------------- big GEMM via mma.sync bf16x3 (HMMA, fp32 accum) ----------------
// grid (200, 2): blockIdx.y = half. Block computes 128 rows x 128 cols of out.
// smem: A hi/lo [128][136] bf16, B hi/lo [128][136] bf16 (pad-8 => conflict-free
// fragment LDS: bank = 4*row + tg). 8 warps in 2x4; warp tile 64x32.
#define PAD 136

__device__ __forceinline__ void mma16816(float* c, const uint32_t* a, const uint32_t* b) {
    asm volatile(
        "mma.sync.aligned.m16n8k16.row.col.f32.bf16.bf16.f32 "
        "{%0,%1,%2,%3}, {%4,%5,%6,%7}, {%8,%9}, {%0,%1,%2,%3};"
        : "+f"(c[0]), "+f"(c[1]), "+f"(c[2]), "+f"(c[3])
        : "r"(a[0]), "r"(a[1]), "r"(a[2]), "r"(a[3]), "r"(b[0]), "r"(b[1]));
}

__global__ __launch_bounds__(256)
void gemm_mma_kernel(const float* __restrict__ X, float* __restrict__ out) {
    extern __shared__ __nv_bfloat16 sb[];
    __nv_bfloat16* Ah = sb;                  // [128][PAD]
    __nv_bfloat16* Al = Ah + 128 * PAD;
    __nv_bfloat16* Bh = Al + 128 * PAD;
    __nv_bfloat16* Bl = Bh + 128 * PAD;

    const int half = blockIdx.y;
    const int row0 = blockIdx.x * 128;
    const int tid = threadIdx.x;

    // ---- stage A: X[row0+r][half*128 + c], split hi/lo ----
    for (int idx = tid; idx < 128 * 32; idx += 256) {
        int r = idx >> 5;
        int c = (idx & 31) * 4;
        float4 v = *(const float4*)(X + (size_t)(row0 + r) * 256 + half * 128 + c);
        float vv[4] = {v.x, v.y, v.z, v.w};
        uint32_t hp[2], lp[2];
#pragma unroll
        for (int q = 0; q < 2; q++) {
            __nv_bfloat16 h0 = __float2bfloat16(vv[2 * q]);
            __nv_bfloat16 h1 = __float2bfloat16(vv[2 * q + 1]);
            __nv_bfloat16 l0 = __float2bfloat16(vv[2 * q] - __bfloat162float(h0));
            __nv_bfloat16 l1 = __float2bfloat16(vv[2 * q + 1] - __bfloat162float(h1));
            hp[q] = ((uint32_t)__bfloat16_as_ushort(h1) << 16) | __bfloat16_as_ushort(h0);
            lp[q] = ((uint32_t)__bfloat16_as_ushort(l1) << 16) | __bfloat16_as_ushort(l0);
        }
        *(uint2*)(Ah + r * PAD + c) = make_uint2(hp[0], hp[1]);
        *(uint2*)(Al + r * PAD + c) = make_uint2(lp[0], lp[1]);
    }
    // ---- stage B: prepped W^T[half][n][k] hi/lo ----
    const __nv_bfloat16* wh = g_WtH + (size_t)half * 16384;
    const __nv_bfloat16* wl = g_WtL + (size_t)half * 16384;
    for (int idx = tid; idx < 128 * 32; idx += 256) {
        int n = idx >> 5;
        int k = (idx & 31) * 4;
        *(uint2*)(Bh + n * PAD + k) = *(const uint2*)(wh + (size_t)n * 128 + k);
        *(uint2*)(Bl + n * PAD + k) = *(const uint2*)(wl + (size_t)n * 128 + k);
    }
    __syncthreads();

    const int wid = tid >> 5;
    const int lane = tid & 31;
    const int g = lane >> 2;     // group row
    const int tg = lane & 3;     // thread in group
    const int wr = (wid >> 2) * 64;   // warp row base within tile
    const int wc = (wid & 3) * 32;    // warp col base within tile

    float acc[4][4][4];
#pragma unroll
    for (int i = 0; i < 4; i++)
#pragma unroll
        for (int j = 0; j < 4; j++)
#pragma unroll
            for (int q = 0; q < 4; q++) acc[i][j][q] = 0.f;

#pragma unroll 2
    for (int ks = 0; ks < 8; ks++) {
        const int k0 = ks * 16 + tg * 2;
        uint32_t ah[4][4], al[4][4], bh[4][2], bl[4][2];
#pragma unroll
        for (int i = 0; i < 4; i++) {
            int r = wr + i * 16 + g;
            ah[i][0] = *(const uint32_t*)(Ah + r * PAD + k0);
            ah[i][1] = *(const uint32_t*)(Ah + (r + 8) * PAD + k0);
            ah[i][2] = *(const uint32_t*)(Ah + r * PAD + k0 + 8);
            ah[i][3] = *(const uint32_t*)(Ah + (r + 8) * PAD + k0 + 8);
            al[i][0] = *(const uint32_t*)(Al + r * PAD + k0);
            al[i][1] = *(const uint32_t*)(Al + (r + 8) * PAD + k0);
            al[i][2] = *(const uint32_t*)(Al + r * PAD + k0 + 8);
            al[i][3] = *(const uint32_t*)(Al + (r + 8) * PAD + k0 + 8);
        }
#pragma unroll
        for (int j = 0; j < 4; j++) {
            int n = wc + j * 8 + g;
            bh[j][0] = *(const uint32_t*)(Bh + n * PAD + k0);
            bh[j][1] = *(const uint32_t*)(Bh + n * PAD + k0 + 8);
            bl[j][0] = *(const uint32_t*)(Bl + n * PAD + k0);
            bl[j][1] = *(const uint32_t*)(Bl + n * PAD + k0 + 8);
        }
#pragma unroll
        for (int i = 0; i < 4; i++)
#pragma unroll
            for (int j = 0; j < 4; j++) {
                mma16816(acc[i][j], ah[i], bh[j]);
                mma16816(acc[i][j], al[i], bh[j]);
                mma16816(acc[i][j], ah[i], bl[j]);
            }
    }

    // ---- epilogue: relu + STG.64 ----
    const int colg = half * 128 + wc;
#pragma unroll
    for (int i = 0; i < 4; i++) {
        int r = row0 + wr + i * 16 + g;
#pragma unroll
        for (int j = 0; j < 4; j++) {
            int cgl = colg + j * 8 + tg * 2;
            float2 o0, o1;
            o0.x = fmaxf(acc[i][j][0], 0.f);
            o0.y = fmaxf(acc[i][j][1], 0.f);
            o1.x = fmaxf(acc[i][j][2], 0.f);
            o1.y = fmaxf(acc[i][j][3], 0.f);
            *(float2*)(out + (size_t)r * 256 + cgl) = o0;
            *(float2*)(out + (size_t)(r + 8) * 256 + cgl) = o1;
        }
    }
}

// ---------------- small GEMM + ReLU (tiled, W in smem) ----------------
template <int K>
__global__ __launch_bounds__(256)
void gemm_small_kernel(const float* __restrict__ A0, const float* __restrict__ W0,
                       const float* __restrict__ A1, const float* __restrict__ W1,
                       float* __restrict__ out) {
    extern __shared__ float sm[];
    float* As = sm;             // [K][32] transposed
    float* Bs = sm + K * 32;    // [K][64]

    const int half = blockIdx.y >> 1;
    const float* A = half ? A1 : A0;
    const float* W = half ? W1 : W0;
    const int wcol0 = (blockIdx.y & 1) * 64;
    const int row0 = blockIdx.x * 32;
    const int tid = threadIdx.x;

    for (int idx = tid; idx < 32 * (K / 4); idx += 256) {
        int r  = idx & 31;
        int k4 = (idx >> 5) * 4;
        float4 v = *(const float4*)(A + (size_t)(row0 + r) * 256 + k4);
        As[(k4 + 0) * 32 + r] = v.x;
        As[(k4 + 1) * 32 + r] = v.y;
        As[(k4 + 2) * 32 + r] = v.z;
        As[(k4 + 3) * 32 + r] = v.w;
    }
    for (int idx = tid; idx < K * 16; idx += 256) {
        int k = idx >> 4;
        int j4 = (idx & 15) * 4;
        *(float4*)(Bs + k * 64 + j4) =
            *(const float4*)(W + (size_t)k * 128 + wcol0 + j4);
    }
    __syncthreads();

    const int rr = (tid & 15) * 2;
    const int cc = (tid >> 4) * 4;

    float acc[2][4];
#pragma unroll
    for (int i = 0; i < 2; i++)
#pragma unroll
        for (int j = 0; j < 4; j++) acc[i][j] = 0.f;

#pragma unroll 8
    for (int k = 0; k < K; k++) {
        float2 a = *(const float2*)(As + k * 32 + rr);
        float4 b = *(const float4*)(Bs + k * 64 + cc);
        acc[0][0] = fmaf(a.x, b.x, acc[0][0]);
        acc[0][1] = fmaf(a.x, b.y, acc[0][1]);
        acc[0][2] = fmaf(a.x, b.z, acc[0][2]);
        acc[0][3] = fmaf(a.x, b.w, acc[0][3]);
        acc[1][0] = fmaf(a.y, b.x, acc[1][0]);
        acc[1][1] = fmaf(a.y, b.y, acc[1][1]);
        acc[1][2] = fmaf(a.y, b.z, acc[1][2]);
        acc[1][3] = fmaf(a.y, b.w, acc[1][3]);
    }

    const int ncol = blockIdx.y * 64 + cc;
#pragma unroll
    for (int i = 0; i < 2; i++) {
        float4 o;
        o.x = fmaxf(acc[i][0], 0.f); o.y = fmaxf(acc[i][1], 0.f);
        o.z = fmaxf(acc[i][2], 0.f); o.w = fmaxf(acc[i][3], 0.f);
        *(float4*)(out + (size_t)(row0 + rr + i) * 256 + ncol) = o;
    }
}

// ---------------- mean over S1 of Y1 -> M1 ----------------
__global__ void mean25_kernel() {
    int t = blockIdx.x * blockDim.x + threadIdx.x;
    if (t >= NB * 64) return;
    int b = t >> 6;
    int q = t & 63;
    const float4* base = (const float4*)g_Y1 + (size_t)b * NS1 * 64 + q;
    float4 acc = make_float4(0.f, 0.f, 0.f, 0.f);
#pragma unroll
    for (int j = 0; j < NS1; j++) {
        float4 v = base[(size_t)j * 64];
        acc.x += v.x; acc.y += v.y; acc.z += v.z; acc.w += v.w;
    }
    const float s = 1.0f / NS1;
    acc.x *= s; acc.y *= s; acc.z *= s; acc.w *= s;
    ((float4*)g_M1)[(size_t)b * 64 + q] = acc;
}

// ---------------- launch ----------------
extern "C" void kernel_launch(void* const* d_in, const int* in_sizes, int n_in,
                              void* d_out, int out_size) {
    const float* feat = (const float*)d_in[0];
    const float* ws0  = (const float*)d_in[1];
    const float* wn0  = (const float*)d_in[2];
    const float* ws1  = (const float*)d_in[3];
    const float* wn1  = (const float*)d_in[4];
    const int*   s0   = (const int*)d_in[5];
    const int*   s1   = (const int*)d_in[6];
    const int*   s2   = (const int*)d_in[7];
    float* out = (float*)d_out;

    float *pX1, *pX0, *pY0, *pM1, *pY1;
    cudaGetSymbolAddress((void**)&pX1, g_X1);
    cudaGetSymbolAddress((void**)&pY1, g_Y1);
    cudaGetSymbolAddress((void**)&pX0, g_X0);
    cudaGetSymbolAddress((void**)&pY0, g_Y0);
    cudaGetSymbolAddress((void**)&pM1, g_M1);

    const size_t smMMA  = (size_t)4 * 128 * PAD * sizeof(__nv_bfloat16);   // 136 KB
    const size_t smS128 = (size_t)(128 * 32 + 128 * 64) * sizeof(float);   //  48 KB
    const size_t smS256 = (size_t)(256 * 32 + 256 * 64) * sizeof(float);   //  96 KB
    cudaFuncSetAttribute(gemm_mma_kernel,
                         cudaFuncAttributeMaxDynamicSharedMemorySize, (int)smMMA);
    cudaFuncSetAttribute(gemm_small_kernel<128>,
                         cudaFuncAttributeMaxDynamicSharedMemorySize, (int)smS128);
    cudaFuncSetAttribute(gemm_small_kernel<256>,
                         cudaFuncAttributeMaxDynamicSharedMemorySize, (int)smS256);

    // 1) prep W0/W1 -> transposed bf16 hi/lo
    prep_w_kernel<<<32, 256>>>(ws0, wn0);
    // 2) X1 = [h1_self | mean_S2(h2)]
    gather1_kernel<<<(ROWS1 * 32 + 255) / 256, 256>>>(feat, s1, s2);
    // 3) X0 = [h0 | mean_S1(h1)]
    gather0_kernel<<<(NB * 32 + 255) / 256, 256>>>(feat, s0);
    // 4) Y1 = relu([X1s@Ws0 | X1n@Wn0])  — HMMA, profiled position
    gemm_mma_kernel<<<dim3(ROWS1 / 128, 2), 256, smMMA>>>(pX1, pY1);
    // 5) Y0 = relu([X0s@Ws0 | X0n@Wn0])
    gemm_small_kernel<128><<<dim3(NB / 32, 4), 256, smS128>>>(pX0, ws0, pX0 + 128, wn0, pY0);
    // 6) M1 = mean_S1(Y1)
    mean25_kernel<<<(NB * 64 + 255) / 256, 256>>>();
    // 7) out = relu([Y0@Ws1 | M1@Wn1])
    gemm_small_kernel<256><<<dim3(NB / 32, 4), 256, smS256>>>(pY0, ws1, pM1, wn1, out);
}

// round 6
// speedup vs baseline: 1.7737x; 1.2408x over previous
#include <cuda_runtime.h>
#include <cuda_bf16.h>
#include <cstdint>

#define NB   1024
#define NS1  25
#define NS2  10
#define DF   128
#define ROWS1 (NB * NS1)   // 25600

// ---------------- scratch (no allocations allowed) ----------------
__device__ float g_X1[(size_t)ROWS1 * 256];  // fp32 [25600][self|meanS2] (for gather0)
__device__ __align__(16) __nv_bfloat16 g_X1h[(size_t)ROWS1 * 256];  // bf16 hi
__device__ __align__(16) __nv_bfloat16 g_X1l[(size_t)ROWS1 * 256];  // bf16 lo
__device__ float g_Y1[(size_t)ROWS1 * 256];
__device__ float g_X0[(size_t)NB * 256];
__device__ float g_Y0[(size_t)NB * 256];
__device__ float g_M1[(size_t)NB * 256];
__device__ __align__(16) __nv_bfloat16 g_WtH[2 * 128 * 128];  // W^T hi, [half][n][k]
__device__ __align__(16) __nv_bfloat16 g_WtL[2 * 128 * 128];  // W^T lo

// ---------------- helpers ----------------
__device__ __forceinline__ void split4(const float4& v, uint2& hi, uint2& lo) {
    float vv[4] = {v.x, v.y, v.z, v.w};
    uint32_t hp[2], lp[2];
#pragma unroll
    for (int q = 0; q < 2; q++) {
        __nv_bfloat16 h0 = __float2bfloat16(vv[2 * q]);
        __nv_bfloat16 h1 = __float2bfloat16(vv[2 * q + 1]);
        __nv_bfloat16 l0 = __float2bfloat16(vv[2 * q] - __bfloat162float(h0));
        __nv_bfloat16 l1 = __float2bfloat16(vv[2 * q + 1] - __bfloat162float(h1));
        hp[q] = ((uint32_t)__bfloat16_as_ushort(h1) << 16) | __bfloat16_as_ushort(h0);
        lp[q] = ((uint32_t)__bfloat16_as_ushort(l1) << 16) | __bfloat16_as_ushort(l0);
    }
    hi = make_uint2(hp[0], hp[1]);
    lo = make_uint2(lp[0], lp[1]);
}
__device__ __forceinline__ uint32_t smem_to_u32(const void* p) {
    uint32_t a;
    asm("{ .reg .u64 t; cvta.to.shared.u64 t, %1; cvt.u32.u64 %0, t; }"
        : "=r"(a) : "l"(p));
    return a;
}
#define CP_ASYNC16(dst_u32, src_ptr) \
    asm volatile("cp.async.cg.shared.global [%0], [%1], 16;" \
        :: "r"(dst_u32), "l"(src_ptr) : "memory")
#define CP_ASYNC_WAIT_ALL() \
    asm volatile("cp.async.commit_group;\ncp.async.wait_group 0;" ::: "memory")

__device__ __forceinline__ void mma16816(float* c, const uint32_t* a, const uint32_t* b) {
    asm volatile(
        "mma.sync.aligned.m16n8k16.row.col.f32.bf16.bf16.f32 "
        "{%0,%1,%2,%3}, {%4,%5,%6,%7}, {%8,%9}, {%0,%1,%2,%3};"
        : "+f"(c[0]), "+f"(c[1]), "+f"(c[2]), "+f"(c[3])
        : "r"(a[0]), "r"(a[1]), "r"(a[2]), "r"(a[3]), "r"(b[0]), "r"(b[1]));
}

// ---------------- prep: transpose + bf16-split the layer-0 weights ----------------
__global__ void prep_w_kernel(const float* __restrict__ w0,
                              const float* __restrict__ w1) {
    __shared__ float t[32][33];
    int b = blockIdx.x;
    int half = b >> 4;
    int tile = b & 15;
    int tr = (tile >> 2) * 32;   // k base
    int tc = (tile & 3) * 32;    // n base
    const float* W = half ? w1 : w0;
    int tx = threadIdx.x & 31, ty = threadIdx.x >> 5;   // 32x8
#pragma unroll
    for (int p = 0; p < 32; p += 8)
        t[ty + p][tx] = W[(size_t)(tr + ty + p) * 128 + tc + tx];
    __syncthreads();
#pragma unroll
    for (int p = 0; p < 32; p += 8) {
        int n = tc + ty + p, k = tr + tx;
        float v = t[tx][ty + p];
        __nv_bfloat16 h = __float2bfloat16(v);
        __nv_bfloat16 l = __float2bfloat16(v - __bfloat162float(h));
        size_t o = ((size_t)half * 128 + n) * 128 + k;
        g_WtH[o] = h;
        g_WtL[o] = l;
    }
}

// ---------------- gather1: self + meanS2, emits fp32 AND bf16 hi/lo ----------------
__global__ void gather1_kernel(const float* __restrict__ feat,
                               const int* __restrict__ s1,
                               const int* __restrict__ s2) {
    int warp = (blockIdx.x * blockDim.x + threadIdx.x) >> 5;
    int lane = threadIdx.x & 31;
    if (warp >= ROWS1) return;
    int c = lane * 4;

    long iself = s1[warp];
    float4 sv = *(const float4*)(feat + iself * DF + c);

    const int* p = s2 + (size_t)warp * NS2;
    int idx[NS2];
#pragma unroll
    for (int j = 0; j < NS2; j++) idx[j] = p[j];

    float4 acc = make_float4(0.f, 0.f, 0.f, 0.f);
#pragma unroll
    for (int j = 0; j < NS2; j++) {
        float4 v = *(const float4*)(feat + (long)idx[j] * DF + c);
        acc.x += v.x; acc.y += v.y; acc.z += v.z; acc.w += v.w;
    }
    const float s = 1.0f / NS2;
    acc.x *= s; acc.y *= s; acc.z *= s; acc.w *= s;

    size_t base = (size_t)warp * 256 + c;
    *(float4*)(g_X1 + base) = sv;
    *(float4*)(g_X1 + base + 128) = acc;

    uint2 h, l;
    split4(sv, h, l);
    *(uint2*)(g_X1h + base) = h;
    *(uint2*)(g_X1l + base) = l;
    split4(acc, h, l);
    *(uint2*)(g_X1h + base + 128) = h;
    *(uint2*)(g_X1l + base + 128) = l;
}

__global__ void gather0_kernel(const float* __restrict__ feat,
                               const int* __restrict__ s0) {
    int warp = (blockIdx.x * blockDim.x + threadIdx.x) >> 5;
    int lane = threadIdx.x & 31;
    if (warp >= NB) return;
    int c = lane * 4;

    long iself = s0[warp];
    *(float4*)(g_X0 + (size_t)warp * 256 + c) =
        *(const float4*)(feat + iself * DF + c);

    float4 acc = make_float4(0.f, 0.f, 0.f, 0.f);
#pragma unroll
    for (int j = 0; j < NS1; j++) {
        float4 v = *(const float4*)(g_X1 + ((size_t)warp * NS1 + j) * 256 + c);
        acc.x += v.x; acc.y += v.y; acc.z += v.z; acc.w += v.w;
    }
    const float s = 1.0f / NS1;
    acc.x *= s; acc.y *= s; acc.z *= s; acc.w *= s;
    *(float4*)(g_X0 + (size_t)warp * 256 + 128 + c) = acc;
}

// ---------------- big GEMM via mma.sync bf16x3 (cp.async staging) ----------------
// grid (400, 2): 64 rows x 128 cols per CTA. smem 104.4KB => 2 CTAs/SM.
// PAD rows to 272B (136 bf16): fragment LDS bank = (4g+tg)%32, conflict-free.
#define PADB 272   // row pitch in bytes

__global__ __launch_bounds__(256)
void gemm_mma_kernel(float* __restrict__ out) {
    extern __shared__ char sb[];
    const uint32_t OFF_AH = 0;
    const uint32_t OFF_AL = 64 * PADB;            // 17408
    const uint32_t OFF_BH = 2 * 64 * PADB;        // 34816
    const uint32_t OFF_BL = OFF_BH + 128 * PADB;  // 69632
    const uint32_t smb = smem_to_u32(sb);

    const int half = blockIdx.y;
    const int row0 = blockIdx.x * 64;
    const int tid = threadIdx.x;

    // ---- stage A (64 rows x 128 bf16, hi+lo) via cp.async ----
    for (int idx = tid; idx < 1024; idx += 256) {
        int r = idx >> 4;
        int ch = (idx & 15) * 16;   // byte offset within 256B row
        size_t gsrc = (size_t)(row0 + r) * 256 + half * 128;
        uint32_t dst = r * PADB + ch;
        CP_ASYNC16(smb + OFF_AH + dst, (const char*)(g_X1h + gsrc) + ch);
        CP_ASYNC16(smb + OFF_AL + dst, (const char*)(g_X1l + gsrc) + ch);
    }
    // ---- stage B (128 n x 128 k bf16, hi+lo) ----
    for (int idx = tid; idx < 2048; idx += 256) {
        int n = idx >> 4;
        int ch = (idx & 15) * 16;
        size_t gsrc = (size_t)half * 16384 + (size_t)n * 128;
        uint32_t dst = n * PADB + ch;
        CP_ASYNC16(smb + OFF_BH + dst, (const char*)(g_WtH + gsrc) + ch);
        CP_ASYNC16(smb + OFF_BL + dst, (const char*)(g_WtL + gsrc) + ch);
    }
    CP_ASYNC_WAIT_ALL();
    __syncthreads();

    const char* Ah = sb + OFF_AH;
    const char* Al = sb + OFF_AL;
    const char* Bh = sb + OFF_BH;
    const char* Bl = sb + OFF_BL;

    const int wid = tid >> 5;
    const int lane = tid & 31;
    const int g = lane >> 2;
    const int tg = lane & 3;
    const int wr = (wid >> 2) * 32;   // warp row base (2 row-groups)
    const int wc = (wid & 3) * 32;    // warp col base (4 col-groups)

    float acc[2][4][4];
#pragma unroll
    for (int i = 0; i < 2; i++)
#pragma unroll
        for (int j = 0; j < 4; j++)
#pragma unroll
            for (int q = 0; q < 4; q++) acc[i][j][q] = 0.f;

#pragma unroll
    for (int ks = 0; ks < 8; ks++) {
        const int kb = (ks * 16 + tg * 2) * 2;   // byte offset of k0 in row
        uint32_t ah[2][4], al[2][4], bh[4][2], bl[4][2];
#pragma unroll
        for (int i = 0; i < 2; i++) {
            int r = wr + i * 16 + g;
            ah[i][0] = *(const uint32_t*)(Ah + r * PADB + kb);
            ah[i][1] = *(const uint32_t*)(Ah + (r + 8) * PADB + kb);
            ah[i][2] = *(const uint32_t*)(Ah + r * PADB + kb + 16);
            ah[i][3] = *(const uint32_t*)(Ah + (r + 8) * PADB + kb + 16);
            al[i][0] = *(const uint32_t*)(Al + r * PADB + kb);
            al[i][1] = *(const uint32_t*)(Al + (r + 8) * PADB + kb);
            al[i][2] = *(const uint32_t*)(Al + r * PADB + kb + 16);
            al[i][3] = *(const uint32_t*)(Al + (r + 8) * PADB + kb + 16);
        }
#pragma unroll
        for (int j = 0; j < 4; j++) {
            int n = wc + j * 8 + g;
            bh[j][0] = *(const uint32_t*)(Bh + n * PADB + kb);
            bh[j][1] = *(const uint32_t*)(Bh + n * PADB + kb + 16);
            bl[j][0] = *(const uint32_t*)(Bl + n * PADB + kb);
            bl[j][1] = *(const uint32_t*)(Bl + n * PADB + kb + 16);
        }
#pragma unroll
        for (int i = 0; i < 2; i++)
#pragma unroll
            for (int j = 0; j < 4; j++) {
                mma16816(acc[i][j], ah[i], bh[j]);
                mma16816(acc[i][j], al[i], bh[j]);
                mma16816(acc[i][j], ah[i], bl[j]);
            }
    }

    // ---- epilogue: relu + STG.64 ----
    const int colg = half * 128 + wc;
#pragma unroll
    for (int i = 0; i < 2; i++) {
        int r = row0 + wr + i * 16 + g;
#pragma unroll
        for (int j = 0; j < 4; j++) {
            int cgl = colg + j * 8 + tg * 2;
            float2 o0, o1;
            o0.x = fmaxf(acc[i][j][0], 0.f);
            o0.y = fmaxf(acc[i][j][1], 0.f);
            o1.x = fmaxf(acc[i][j][2], 0.f);
            o1.y = fmaxf(acc[i][j][3], 0.f);
            *(float2*)(g_Y1 + (size_t)r * 256 + cgl) = o0;
            *(float2*)(g_Y1 + (size_t)(r + 8) * 256 + cgl) = o1;
        }
    }
    (void)out;
}

// ---------------- small GEMM + ReLU (tiled, W in smem) ----------------
template <int K>
__global__ __launch_bounds__(256)
void gemm_small_kernel(const float* __restrict__ A0, const float* __restrict__ W0,
                       const float* __restrict__ A1, const float* __restrict__ W1,
                       float* __restrict__ out) {
    extern __shared__ float sm[];
    float* As = sm;             // [K][32] transposed
    float* Bs = sm + K * 32;    // [K][64]

    const int half = blockIdx.y >> 1;
    const float* A = half ? A1 : A0;
    const float* W = half ? W1 : W0;
    const int wcol0 = (blockIdx.y & 1) * 64;
    const int row0 = blockIdx.x * 32;
    const int tid = threadIdx.x;

    for (int idx = tid; idx < 32 * (K / 4); idx += 256) {
        int r  = idx & 31;
        int k4 = (idx >> 5) * 4;
        float4 v = *(const float4*)(A + (size_t)(row0 + r) * 256 + k4);
        As[(k4 + 0) * 32 + r] = v.x;
        As[(k4 + 1) * 32 + r] = v.y;
        As[(k4 + 2) * 32 + r] = v.z;
        As[(k4 + 3) * 32 + r] = v.w;
    }
    for (int idx = tid; idx < K * 16; idx += 256) {
        int k = idx >> 4;
        int j4 = (idx & 15) * 4;
        *(float4*)(Bs + k * 64 + j4) =
            *(const float4*)(W + (size_t)k * 128 + wcol0 + j4);
    }
    __syncthreads();

    const int rr = (tid & 15) * 2;
    const int cc = (tid >> 4) * 4;

    float acc[2][4];
#pragma unroll
    for (int i = 0; i < 2; i++)
#pragma unroll
        for (int j = 0; j < 4; j++) acc[i][j] = 0.f;

#pragma unroll 8
    for (int k = 0; k < K; k++) {
        float2 a = *(const float2*)(As + k * 32 + rr);
        float4 b = *(const float4*)(Bs + k * 64 + cc);
        acc[0][0] = fmaf(a.x, b.x, acc[0][0]);
        acc[0][1] = fmaf(a.x, b.y, acc[0][1]);
        acc[0][2] = fmaf(a.x, b.z, acc[0][2]);
        acc[0][3] = fmaf(a.x, b.w, acc[0][3]);
        acc[1][0] = fmaf(a.y, b.x, acc[1][0]);
        acc[1][1] = fmaf(a.y, b.y, acc[1][1]);
        acc[1][2] = fmaf(a.y, b.z, acc[1][2]);
        acc[1][3] = fmaf(a.y, b.w, acc[1][3]);
    }

    const int ncol = blockIdx.y * 64 + cc;
#pragma unroll
    for (int i = 0; i < 2; i++) {
        float4 o;
        o.x = fmaxf(acc[i][0], 0.f); o.y = fmaxf(acc[i][1], 0.f);
        o.z = fmaxf(acc[i][2], 0.f); o.w = fmaxf(acc[i][3], 0.f);
        *(float4*)(out + (size_t)(row0 + rr + i) * 256 + ncol) = o;
    }
}

// ---------------- mean over S1 of Y1 -> M1 ----------------
__global__ void mean25_kernel() {
    int t = blockIdx.x * blockDim.x + threadIdx.x;
    if (t >= NB * 64) return;
    int b = t >> 6;
    int q = t & 63;
    const float4* base = (const float4*)g_Y1 + (size_t)b * NS1 * 64 + q;
    float4 acc = make_float4(0.f, 0.f, 0.f, 0.f);
#pragma unroll
    for (int j = 0; j < NS1; j++) {
        float4 v = base[(size_t)j * 64];
        acc.x += v.x; acc.y += v.y; acc.z += v.z; acc.w += v.w;
    }
    const float s = 1.0f / NS1;
    acc.x *= s; acc.y *= s; acc.z *= s; acc.w *= s;
    ((float4*)g_M1)[(size_t)b * 64 + q] = acc;
}

// ---------------- launch ----------------
extern "C" void kernel_launch(void* const* d_in, const int* in_sizes, int n_in,
                              void* d_out, int out_size) {
    const float* feat = (const float*)d_in[0];
    const float* ws0  = (const float*)d_in[1];
    const float* wn0  = (const float*)d_in[2];
    const float* ws1  = (const float*)d_in[3];
    const float* wn1  = (const float*)d_in[4];
    const int*   s0   = (const int*)d_in[5];
    const int*   s1   = (const int*)d_in[6];
    const int*   s2   = (const int*)d_in[7];
    float* out = (float*)d_out;

    float *pX0, *pY0, *pM1, *pY1;
    cudaGetSymbolAddress((void**)&pY1, g_Y1);
    cudaGetSymbolAddress((void**)&pX0, g_X0);
    cudaGetSymbolAddress((void**)&pY0, g_Y0);
    cudaGetSymbolAddress((void**)&pM1, g_M1);

    const size_t smMMA  = (size_t)(2 * 64 + 2 * 128) * PADB;               // 104448
    const size_t smS128 = (size_t)(128 * 32 + 128 * 64) * sizeof(float);   //  48 KB
    const size_t smS256 = (size_t)(256 * 32 + 256 * 64) * sizeof(float);   //  96 KB
    cudaFuncSetAttribute(gemm_mma_kernel,
                         cudaFuncAttributeMaxDynamicSharedMemorySize, (int)smMMA);
    cudaFuncSetAttribute(gemm_small_kernel<128>,
                         cudaFuncAttributeMaxDynamicSharedMemorySize, (int)smS128);
    cudaFuncSetAttribute(gemm_small_kernel<256>,
                         cudaFuncAttributeMaxDynamicSharedMemorySize, (int)smS256);

    // 1) prep W0/W1 -> transposed bf16 hi/lo
    prep_w_kernel<<<32, 256>>>(ws0, wn0);
    // 2) X1 = [h1_self | mean_S2(h2)] (+ bf16 hi/lo copies)
    gather1_kernel<<<(ROWS1 * 32 + 255) / 256, 256>>>(feat, s1, s2);
    // 3) X0 = [h0 | mean_S1(h1)]
    gather0_kernel<<<(NB * 32 + 255) / 256, 256>>>(feat, s0);
    // 4) Y1 = relu([X1s@Ws0 | X1n@Wn0])  — HMMA, profiled position
    gemm_mma_kernel<<<dim3(ROWS1 / 64, 2), 256, smMMA>>>(pY1);
    // 5) Y0 = relu([X0s@Ws0 | X0n@Wn0])
    gemm_small_kernel<128><<<dim3(NB / 32, 4), 256, smS128>>>(pX0, ws0, pX0 + 128, wn0, pY0);
    // 6) M1 = mean_S1(Y1)
    mean25_kernel<<<(NB * 64 + 255) / 256, 256>>>();
    // 7) out = relu([Y0@Ws1 | M1@Wn1])
    gemm_small_kernel<256><<<dim3(NB / 32, 4), 256, smS256>>>(pY0, ws1, pM1, wn1, out);
}